// round 14
// baseline (speedup 1.0000x reference)
#include <cuda_runtime.h>

#define N_NODES 8192
#define F_IN    512
#define F_OUT   64
#define NSPLIT  4
#define JCHUNK  (N_NODES / NSPLIT)   // 2048
#define BM      128
#define BJ      64
#define NT      (JCHUNK / BJ)        // 32 tiles per CTA
#define NTHR_A  256
#define NTHR_H  512

// ---- k_attn smem: header + 2 stages of 48KB (fits 2 CTAs/SM) ----
#define SM_TMEM   0
#define SM_DONE   8                  // done0=8, done1=16
#define SM_FULL   24                 // full0=24, full1=32
#define SM_STAGE0 1024
#define STAGE_SZ  49152
#define OFF_AHI   0                  // 16KB: 128 rows x 64 j bf16
#define OFF_ALO   16384
#define OFF_BHI   32768              // 8KB: 64 feat x 64 j bf16
#define OFF_BLO   40960
#define SM_TOT    (SM_STAGE0 + 2 * STAGE_SZ)   // 99328

// ---- k_hproj_tc smem: header + 2 stages of 48KB ----
#define HP_STAGE_SZ 49152
#define HP_AHI   0
#define HP_ALO   16384
#define HP_BHI   32768
#define HP_BLO   40960
#define KSPLIT_H 2
#define HP_NT    4                   // 4 K-tiles of 64 per CTA (K split in 2)
#define HP_SMTOT (SM_STAGE0 + 2 * HP_STAGE_SZ) // 99328

// fallback (FMA) path smem layout inside the same dynamic buffer
#define BJ_F     32
#define NT_F     (JCHUNK / BJ_F)     // 64
#define WT_PITCH 130
#define HS_PITCH 68
#define SMF_WT   0
#define SMF_HS   (BJ_F * WT_PITCH * 8)

// idesc kind::f16: F32 accum, bf16 A/B, N=64, M=128
#define MMA_IDESC 0x08100490u

#define SW(x) ((x) ^ ((((unsigned)(x)) >> 3) & 0x70u))

#if defined(__CUDA_ARCH_FEAT_SM103_ALL) || defined(__CUDA_ARCH_FEAT_SM100_ALL) || \
    defined(__CUDA_ARCH_FEAT_SM101_ALL) || defined(__CUDA_ARCH_SPECIFIC__)
#define HAS_TC 1
#else
#define HAS_TC 0
#endif

typedef unsigned long long ull;

__device__ float          g_h[N_NODES * F_OUT];
__device__ float          g_hpart[KSPLIT_H][N_NODES * F_OUT];
__device__ unsigned short g_hT_hi[F_OUT * N_NODES];
__device__ unsigned short g_hT_lo[F_OUT * N_NODES];
__device__ unsigned short g_wT_hi[F_OUT * F_IN];   // [n][k] K-major
__device__ unsigned short g_wT_lo[F_OUT * F_IN];
__device__ float          g_s1[N_NODES];
__device__ float          g_s2[N_NODES];
__device__ float          g_p1[N_NODES];    // exp(s1)
__device__ float          g_q1[N_NODES];    // exp(0.2 s1)
__device__ float          g_r2[N_NODES];    // exp(s2)
__device__ float          g_t2[N_NODES];    // exp(0.2 s2)
__device__ float          g_accP[NSPLIT][N_NODES * F_OUT];
__device__ float          g_lP[NSPLIT][N_NODES];

// ---------------- generic helpers ----------------
__device__ __forceinline__ unsigned smem_u32(const void* p) {
    unsigned r;
    asm("{ .reg .u64 t; cvta.to.shared.u64 t, %1; cvt.u32.u64 %0, t; }" : "=r"(r) : "l"(p));
    return r;
}
__device__ __forceinline__ unsigned short bf16of(float v) {
    unsigned short h; asm("cvt.rn.bf16.f32 %0, %1;" : "=h"(h) : "f"(v)); return h;
}
__device__ __forceinline__ void ffma2(ull &d, ull a, ull b) {
    asm("fma.rn.f32x2 %0, %1, %2, %0;" : "+l"(d) : "l"(a), "l"(b));
}
__device__ __forceinline__ ull dup2(float x) {
    ull r; asm("mov.b64 %0, {%1, %1};" : "=l"(r) : "f"(x)); return r;
}
__device__ __forceinline__ float2 unpack2(ull v) {
    float2 r; asm("mov.b64 {%0, %1}, %2;" : "=f"(r.x), "=f"(r.y) : "l"(v)); return r;
}

#if HAS_TC
// ---------------- tcgen05 helpers ('a'-pass only) ----------------
__device__ __forceinline__ unsigned elect_one() {
    unsigned p;
    asm volatile("{ .reg .pred p; elect.sync _|p, 0xFFFFFFFF; selp.b32 %0, 1, 0, p; }" : "=r"(p));
    return p;
}
__device__ __forceinline__ unsigned pack2(float a, float b) {  // lower = a, upper = b
    unsigned r; asm("cvt.rn.bf16x2.f32 %0, %2, %1;" : "=r"(r) : "f"(a), "f"(b)); return r;
}
__device__ __forceinline__ void mma_f16_ss(unsigned d, ull a, ull b, unsigned idesc, unsigned en) {
    asm volatile(
        "{ .reg .pred p; setp.ne.u32 p, %4, 0;\n\t"
        "tcgen05.mma.cta_group::1.kind::f16 [%0], %1, %2, %3, {%5,%5,%5,%5}, p; }"
        :: "r"(d), "l"(a), "l"(b), "r"(idesc), "r"(en), "r"(0u) : "memory");
}
__device__ __forceinline__ void mbar_init(unsigned m, unsigned cnt) {
    asm volatile("mbarrier.init.shared.b64 [%0], %1;" :: "r"(m), "r"(cnt) : "memory");
}
__device__ __forceinline__ void mbar_arrive(unsigned m) {
    asm volatile("mbarrier.arrive.release.cta.shared::cta.b64 _, [%0];" :: "r"(m) : "memory");
}
__device__ __forceinline__ void mbar_wait(unsigned m, unsigned parity) {
    asm volatile(
        "{ .reg .pred P;\n\t"
        "WL_%=: mbarrier.try_wait.parity.acquire.cta.shared::cta.b64 P, [%0], %1, 0x989680;\n\t"
        "@P bra.uni WD_%=;\n\t"
        "bra.uni WL_%=;\n\t"
        "WD_%=: }"
        :: "r"(m), "r"(parity) : "memory");
}
__device__ __forceinline__ void tmem_alloc(unsigned smem_dst, unsigned ncols) {
    asm volatile("tcgen05.alloc.cta_group::1.sync.aligned.shared::cta.b32 [%0], %1;"
                 :: "r"(smem_dst), "r"(ncols) : "memory");
}
__device__ __forceinline__ void tmem_dealloc(unsigned tmem, unsigned ncols) {
    asm volatile("tcgen05.dealloc.cta_group::1.sync.aligned.b32 %0, %1;" :: "r"(tmem), "r"(ncols));
}
__device__ __forceinline__ void tmem_relinquish() {
    asm volatile("tcgen05.relinquish_alloc_permit.cta_group::1.sync.aligned;");
}
__device__ __forceinline__ void tc_commit(unsigned mbar) {
    asm volatile("tcgen05.commit.cta_group::1.mbarrier::arrive::one.shared::cluster.b64 [%0];"
                 :: "r"(mbar) : "memory");
}
__device__ __forceinline__ void fence_async_smem() {
    asm volatile("fence.proxy.async.shared::cta;" ::: "memory");
}
__device__ __forceinline__ void tc_fence_after() {
    asm volatile("tcgen05.fence::after_thread_sync;" ::: "memory");
}
__device__ __forceinline__ void tc_fence_before() {
    asm volatile("tcgen05.fence::before_thread_sync;" ::: "memory");
}
__device__ __forceinline__ void tmem_ld_x32(unsigned* r, unsigned addr) {
    asm volatile(
        "tcgen05.ld.sync.aligned.32x32b.x32.b32 "
        "{%0,%1,%2,%3,%4,%5,%6,%7,%8,%9,%10,%11,%12,%13,%14,%15,"
        "%16,%17,%18,%19,%20,%21,%22,%23,%24,%25,%26,%27,%28,%29,%30,%31}, [%32];"
        : "=r"(r[0]), "=r"(r[1]), "=r"(r[2]), "=r"(r[3]), "=r"(r[4]), "=r"(r[5]), "=r"(r[6]), "=r"(r[7]),
          "=r"(r[8]), "=r"(r[9]), "=r"(r[10]), "=r"(r[11]), "=r"(r[12]), "=r"(r[13]), "=r"(r[14]), "=r"(r[15]),
          "=r"(r[16]), "=r"(r[17]), "=r"(r[18]), "=r"(r[19]), "=r"(r[20]), "=r"(r[21]), "=r"(r[22]), "=r"(r[23]),
          "=r"(r[24]), "=r"(r[25]), "=r"(r[26]), "=r"(r[27]), "=r"(r[28]), "=r"(r[29]), "=r"(r[30]), "=r"(r[31])
        : "r"(addr));
}
__device__ __forceinline__ void tmem_wait_ld() {
    asm volatile("tcgen05.wait::ld.sync.aligned;" ::: "memory");
}
static constexpr ull DESC_BASE_SW128 =
    (2ull << 61) | (1ull << 46) | (64ull << 32) | (1ull << 16);
__device__ __forceinline__ ull smem_desc(unsigned addr) {
    return DESC_BASE_SW128 | ((ull)(addr >> 4) & 0x3FFFull);
}
#endif  // HAS_TC

// ---------------------------------------------------------------------------
// Kernel 0: W[512][64] -> transposed bf16 hi/lo [64][512] (K-major, MMA-ready)
// ---------------------------------------------------------------------------
__global__ __launch_bounds__(512) void k_wprep(const float* __restrict__ W) {
    int e = blockIdx.x * 512 + threadIdx.x;
    int k = e >> 6, n = e & 63;
    float v = W[e];
    unsigned short hb = bf16of(v);
    float fhi = __uint_as_float(((unsigned)hb) << 16);
    unsigned short lb = bf16of(v - fhi);
    g_wT_hi[n * F_IN + k] = hb;
    g_wT_lo[n * F_IN + k] = lb;
}

// ---------------------------------------------------------------------------
// Kernel 1: partial h = input[:, kpart*256:+256] @ W-half via tcgen05.
// grid (64, 2): 128 CTAs -> much better SM coverage than round-13's 64.
// Writes fp32 partial D to g_hpart[kpart]; merge kernel does the epilogue.
// ---------------------------------------------------------------------------
__global__ __launch_bounds__(NTHR_H, 1) void k_hproj_tc(const float* __restrict__ inp,
                                                        const float* __restrict__ W) {
    extern __shared__ char smem[];
    const int tid  = threadIdx.x;
    const int row0 = blockIdx.x * 128;
    const int kp   = blockIdx.y;          // K half (0/1)
    const int kbase = kp * (F_IN / KSPLIT_H);   // 0 or 256

#if HAS_TC
    const unsigned sbase = smem_u32(smem);
    const int wid  = tid >> 5;
    const int lane = tid & 31;

    if (wid == 0) { tmem_alloc(sbase + SM_TMEM, 64); tmem_relinquish(); }
    if (tid == 0) {
        mbar_init(sbase + SM_DONE, 1);
        mbar_init(sbase + SM_DONE + 8, 1);
        mbar_init(sbase + SM_FULL, 16);
        mbar_init(sbase + SM_FULL + 8, 16);
    }
    __syncthreads();
    unsigned tmem;
    asm volatile("ld.shared.b32 %0, [%1];" : "=r"(tmem) : "r"(sbase + SM_TMEM));
    const unsigned doneb = sbase + SM_DONE;
    const unsigned fullb = sbase + SM_FULL;

    const int r  = tid >> 2;
    const int kq = tid & 3;
    const float* inRow = inp + (size_t)(row0 + r) * F_IN + kbase + kq * 16;
    const unsigned aoff0 = SW(r * 128 + kq * 32);
    const unsigned aoff1 = SW(r * 128 + kq * 32 + 16);

    const int bn = tid >> 3, bu = tid & 7;
    const unsigned boff = SW(bn * 128 + bu * 16);
    const unsigned short* wHiP = g_wT_hi + (size_t)bn * F_IN + kbase + bu * 8;
    const unsigned short* wLoP = g_wT_lo + (size_t)bn * F_IN + kbase + bu * 8;

    for (int kt = 0; kt < HP_NT; kt++) {
        const int st = kt & 1;
        char* stage = smem + SM_STAGE0 + st * HP_STAGE_SZ;
        const unsigned mbD = doneb + (st << 3);
        const unsigned mbF = fullb + (st << 3);

        float4 x0 = *(const float4*)(inRow + kt * 64);
        float4 x1 = *(const float4*)(inRow + kt * 64 + 4);
        float4 x2 = *(const float4*)(inRow + kt * 64 + 8);
        float4 x3 = *(const float4*)(inRow + kt * 64 + 12);
        int4 whi = *(const int4*)(wHiP + kt * 64);
        int4 wlo = *(const int4*)(wLoP + kt * 64);

        if (kt >= 2) mbar_wait(mbD, ((kt >> 1) + 1) & 1);

        *(int4*)(stage + HP_BHI + boff) = whi;
        *(int4*)(stage + HP_BLO + boff) = wlo;

        float f[16];
        *(float4*)&f[0] = x0; *(float4*)&f[4] = x1;
        *(float4*)&f[8] = x2; *(float4*)&f[12] = x3;
        unsigned hh[8], ll[8];
#pragma unroll
        for (int i = 0; i < 8; i++) {
            unsigned h = pack2(f[i * 2], f[i * 2 + 1]);
            float fa = __uint_as_float(h << 16);
            float fb = __uint_as_float(h & 0xffff0000u);
            hh[i] = h;
            ll[i] = pack2(f[i * 2] - fa, f[i * 2 + 1] - fb);
        }
        *(int4*)(stage + HP_AHI + aoff0) = make_int4(hh[0], hh[1], hh[2], hh[3]);
        *(int4*)(stage + HP_AHI + aoff1) = make_int4(hh[4], hh[5], hh[6], hh[7]);
        *(int4*)(stage + HP_ALO + aoff0) = make_int4(ll[0], ll[1], ll[2], ll[3]);
        *(int4*)(stage + HP_ALO + aoff1) = make_int4(ll[4], ll[5], ll[6], ll[7]);

        fence_async_smem();
        __syncwarp();
        if (elect_one()) mbar_arrive(mbF);

        if (wid == 15) {
            mbar_wait(mbF, (kt >> 1) & 1);
            if (elect_one()) {
                const unsigned sb = sbase + SM_STAGE0 + st * HP_STAGE_SZ;
                ull dA[3] = {smem_desc(sb + HP_AHI), smem_desc(sb + HP_AHI),
                             smem_desc(sb + HP_ALO)};
                ull dB[3] = {smem_desc(sb + HP_BHI), smem_desc(sb + HP_BLO),
                             smem_desc(sb + HP_BHI)};
#pragma unroll
                for (int p = 0; p < 3; p++)
#pragma unroll
                    for (int k = 0; k < 4; k++)
                        mma_f16_ss(tmem, dA[p] + k * 2, dB[p] + k * 2, MMA_IDESC,
                                   !(kt == 0 && p == 0 && k == 0));
                tc_commit(mbD);
            }
        }
    }

    // drain: per barrier 2 commits; loop consumed none beyond phase 0; wait
    // the last phase index HP_NT/2-1 = 1 on each (in order).
    mbar_wait(doneb,     ((HP_NT / 2) - 1) & 1);
    mbar_wait(doneb + 8, ((HP_NT / 2) - 1) & 1);
    tc_fence_after();
    if (wid < 4) {
        unsigned d0[32], d1[32];
        tmem_ld_x32(d0, tmem);
        tmem_ld_x32(d1, tmem + 32);
        tmem_wait_ld();
        tc_fence_before();
        float* dst = &g_hpart[kp][(size_t)(row0 + wid * 32 + lane) * F_OUT];
#pragma unroll
        for (int c = 0; c < 8; c++) {
            *(float4*)&dst[c * 4] = make_float4(
                __uint_as_float(d0[c * 4]), __uint_as_float(d0[c * 4 + 1]),
                __uint_as_float(d0[c * 4 + 2]), __uint_as_float(d0[c * 4 + 3]));
            *(float4*)&dst[32 + c * 4] = make_float4(
                __uint_as_float(d1[c * 4]), __uint_as_float(d1[c * 4 + 1]),
                __uint_as_float(d1[c * 4 + 2]), __uint_as_float(d1[c * 4 + 3]));
        }
    }
    __syncthreads();
    if (wid == 0) tmem_dealloc(tmem, 64);

#else  // ---------------- fallback (non-'a' pass): half-K partial ----------
    const int r  = tid >> 2;
    const int cq = tid & 3;
    float acc[16];
#pragma unroll
    for (int i = 0; i < 16; i++) acc[i] = 0.f;
    for (int k = kbase; k < kbase + F_IN / KSPLIT_H; k++) {
        float v = inp[(size_t)(row0 + r) * F_IN + k];
        const float* wr = W + (size_t)k * F_OUT + cq * 16;
#pragma unroll
        for (int i = 0; i < 16; i++) acc[i] += v * wr[i];
    }
    float* dst = &g_hpart[kp][(size_t)(row0 + r) * F_OUT + cq * 16];
#pragma unroll
    for (int i = 0; i < 4; i++)
        *(float4*)&dst[i * 4] = make_float4(acc[i * 4], acc[i * 4 + 1],
                                            acc[i * 4 + 2], acc[i * 4 + 3]);
#endif
}

// ---------------------------------------------------------------------------
// Kernel 1b: merge K-halves -> h, hT hi/lo, scores s1/s2 + exp tables.
// grid 64 x 512 threads; 4 threads per row (16 feats each).
// ---------------------------------------------------------------------------
__global__ __launch_bounds__(512) void k_hmerge(const float* __restrict__ a) {
    const int tid = threadIdx.x;
    const int r   = tid >> 2;
    const int cq  = tid & 3;
    const int row = blockIdx.x * 128 + r;

    const float* p0 = &g_hpart[0][(size_t)row * F_OUT + cq * 16];
    const float* p1 = &g_hpart[1][(size_t)row * F_OUT + cq * 16];
    float v[16];
#pragma unroll
    for (int i = 0; i < 4; i++) {
        float4 a4 = *(const float4*)&p0[i * 4];
        float4 b4 = *(const float4*)&p1[i * 4];
        v[i * 4 + 0] = a4.x + b4.x;
        v[i * 4 + 1] = a4.y + b4.y;
        v[i * 4 + 2] = a4.z + b4.z;
        v[i * 4 + 3] = a4.w + b4.w;
    }

    float* hrow = &g_h[(size_t)row * F_OUT + cq * 16];
#pragma unroll
    for (int i = 0; i < 4; i++)
        *(float4*)&hrow[i * 4] = make_float4(v[i * 4], v[i * 4 + 1], v[i * 4 + 2], v[i * 4 + 3]);

    float s1p = 0.f, s2p = 0.f;
#pragma unroll
    for (int i = 0; i < 16; i++) {
        int f = cq * 16 + i;
        float x = v[i];
        unsigned short hb = bf16of(x);
        float fhi = __uint_as_float(((unsigned)hb) << 16);
        unsigned short lb = bf16of(x - fhi);
        g_hT_hi[(size_t)f * N_NODES + row] = hb;
        g_hT_lo[(size_t)f * N_NODES + row] = lb;
        s1p += x * __ldg(&a[f]);
        s2p += x * __ldg(&a[64 + f]);
    }
    s1p += __shfl_xor_sync(0xffffffffu, s1p, 1);
    s1p += __shfl_xor_sync(0xffffffffu, s1p, 2);
    s2p += __shfl_xor_sync(0xffffffffu, s2p, 1);
    s2p += __shfl_xor_sync(0xffffffffu, s2p, 2);
    if (cq == 0) {
        g_s1[row] = s1p;  g_s2[row] = s2p;
        g_p1[row] = __expf(s1p);
        g_q1[row] = __expf(0.2f * s1p);
        g_r2[row] = __expf(s2p);
        g_t2[row] = __expf(0.2f * s2p);
    }
}

// ---------------------------------------------------------------------------
// Kernel 2: fused masked attention-weight x h via tcgen05. BJ=64 tiles,
// 256 threads, grid (64, 4) = 256 CTAs, 2 CTAs/SM co-residency.
// (UNCHANGED from round 13 — it is the proven winner.)
// ---------------------------------------------------------------------------
__global__ __launch_bounds__(NTHR_A, 2) void k_attn_tc(const int* __restrict__ adj) {
    extern __shared__ char smem[];
    const int tid  = threadIdx.x;
    const int row0 = blockIdx.x * BM;
    const int s    = blockIdx.y;
    const int jbase = s * JCHUNK;

#if HAS_TC
    const unsigned sbase = smem_u32(smem);
    const int wid  = tid >> 5;
    const int lane = tid & 31;

    if (wid == 0) { tmem_alloc(sbase + SM_TMEM, 64); tmem_relinquish(); }
    if (tid == 0) {
        mbar_init(sbase + SM_DONE, 1);
        mbar_init(sbase + SM_DONE + 8, 1);
        mbar_init(sbase + SM_FULL, 8);
        mbar_init(sbase + SM_FULL + 8, 8);
    }
    __syncthreads();
    unsigned tmem;
    asm volatile("ld.shared.b32 %0, [%1];" : "=r"(tmem) : "r"(sbase + SM_TMEM));
    const unsigned doneb = sbase + SM_DONE;
    const unsigned fullb = sbase + SM_FULL;

    const int r2 = lane >> 4;
    const int jc = lane & 15;

    float P[8], Q[8], lp[8];
#pragma unroll
    for (int u = 0; u < 8; u++) {
        int r = row0 + wid * 16 + u * 2 + r2;
        P[u] = g_p1[r]; Q[u] = g_q1[r];
        lp[u] = 0.f;
    }
    const int* adjBase = adj + (size_t)(row0 + wid * 16 + r2) * N_NODES + jbase + jc * 4;

    const int bfeat = tid >> 2;
    const int bunit = (tid & 3) * 2;
    const unsigned boff0 = SW(bfeat * 128 + bunit * 16);
    const unsigned boff1 = SW(bfeat * 128 + (bunit + 1) * 16);
    const unsigned short* bHiP = g_hT_hi + (size_t)bfeat * N_NODES + bunit * 8;
    const unsigned short* bLoP = g_hT_lo + (size_t)bfeat * N_NODES + bunit * 8;

    int4 aCur[8];
#pragma unroll
    for (int u = 0; u < 8; u++)
        aCur[u] = *(const int4*)(adjBase + (size_t)u * 2 * N_NODES);
    int4 bh0 = *(const int4*)(bHiP + jbase);
    int4 bh1 = *(const int4*)(bHiP + jbase + 8);
    int4 bl0 = *(const int4*)(bLoP + jbase);
    int4 bl1 = *(const int4*)(bLoP + jbase + 8);
    float4 Rc = *(const float4*)(g_r2 + jbase + jc * 4);
    float4 Tc = *(const float4*)(g_t2 + jbase + jc * 4);

    for (int t = 0; t < NT; t++) {
        const int st = t & 1;
        char* stage = smem + SM_STAGE0 + st * STAGE_SZ;
        const unsigned mbD = doneb + (st << 3);
        const unsigned mbF = fullb + (st << 3);

        if (t >= 2) mbar_wait(mbD, ((t >> 1) + 1) & 1);

        *(int4*)(stage + OFF_BHI + boff0) = bh0;
        *(int4*)(stage + OFF_BHI + boff1) = bh1;
        *(int4*)(stage + OFF_BLO + boff0) = bl0;
        *(int4*)(stage + OFF_BLO + boff1) = bl1;

        float4 Ru = Rc, Tu = Tc;
        if (t + 1 < NT) {
            const int jn = jbase + (t + 1) * BJ;
            bh0 = *(const int4*)(bHiP + jn);
            bh1 = *(const int4*)(bHiP + jn + 8);
            bl0 = *(const int4*)(bLoP + jn);
            bl1 = *(const int4*)(bLoP + jn + 8);
            Rc = *(const float4*)(g_r2 + jn + jc * 4);
            Tc = *(const float4*)(g_t2 + jn + jc * 4);
        }

#pragma unroll
        for (int u = 0; u < 8; u++) {
            int4 av = aCur[u];
            if (t + 1 < NT)
                aCur[u] = *(const int4*)(adjBase + (size_t)u * 2 * N_NODES + (t + 1) * BJ);

            float w0 = (av.x > 0) ? fmaxf(P[u] * Ru.x, Q[u] * Tu.x) : 0.f;
            float w1 = (av.y > 0) ? fmaxf(P[u] * Ru.y, Q[u] * Tu.y) : 0.f;
            float w2 = (av.z > 0) ? fmaxf(P[u] * Ru.z, Q[u] * Tu.z) : 0.f;
            float w3 = (av.w > 0) ? fmaxf(P[u] * Ru.w, Q[u] * Tu.w) : 0.f;
            lp[u] += (w0 + w1) + (w2 + w3);

            unsigned hh01 = pack2(w0, w1);
            unsigned hh23 = pack2(w2, w3);
            float f0 = __uint_as_float(hh01 << 16);
            float f1 = __uint_as_float(hh01 & 0xffff0000u);
            float f2 = __uint_as_float(hh23 << 16);
            float f3 = __uint_as_float(hh23 & 0xffff0000u);
            unsigned ll01 = pack2(w0 - f0, w1 - f1);
            unsigned ll23 = pack2(w2 - f2, w3 - f3);

            const int rloc = wid * 16 + u * 2 + r2;
            const unsigned aoff = SW(rloc * 128 + jc * 8);
            *(uint2*)(stage + OFF_AHI + aoff) = make_uint2(hh01, hh23);
            *(uint2*)(stage + OFF_ALO + aoff) = make_uint2(ll01, ll23);
        }

        fence_async_smem();
        __syncwarp();
        if (elect_one()) mbar_arrive(mbF);

        if (wid == 7) {
            mbar_wait(mbF, (t >> 1) & 1);
            if (elect_one()) {
                const unsigned sb = sbase + SM_STAGE0 + st * STAGE_SZ;
                ull dA[3] = {smem_desc(sb + OFF_AHI), smem_desc(sb + OFF_AHI),
                             smem_desc(sb + OFF_ALO)};
                ull dB[3] = {smem_desc(sb + OFF_BHI), smem_desc(sb + OFF_BLO),
                             smem_desc(sb + OFF_BHI)};
#pragma unroll
                for (int p = 0; p < 3; p++)
#pragma unroll
                    for (int k = 0; k < 4; k++)
                        mma_f16_ss(tmem, dA[p] + k * 2, dB[p] + k * 2, MMA_IDESC,
                                   !(t == 0 && p == 0 && k == 0));
                tc_commit(mbD);
            }
        }
    }

#pragma unroll
    for (int u = 0; u < 8; u++) {
        float v = lp[u];
        v += __shfl_xor_sync(0xffffffffu, v, 1);
        v += __shfl_xor_sync(0xffffffffu, v, 2);
        v += __shfl_xor_sync(0xffffffffu, v, 4);
        v += __shfl_xor_sync(0xffffffffu, v, 8);
        if (jc == 0)
            g_lP[s][row0 + wid * 16 + u * 2 + r2] = v;
    }

    mbar_wait(doneb,     ((NT / 2) - 1) & 1);
    mbar_wait(doneb + 8, ((NT / 2) - 1) & 1);
    tc_fence_after();
    if (wid < 4) {
        unsigned d0[32], d1[32];
        tmem_ld_x32(d0, tmem);
        tmem_ld_x32(d1, tmem + 32);
        tmem_wait_ld();
        tc_fence_before();
        float* dst = &g_accP[s][(size_t)(row0 + wid * 32 + lane) * F_OUT];
#pragma unroll
        for (int c = 0; c < 8; c++) {
            *(float4*)&dst[c * 4] = make_float4(
                __uint_as_float(d0[c * 4]), __uint_as_float(d0[c * 4 + 1]),
                __uint_as_float(d0[c * 4 + 2]), __uint_as_float(d0[c * 4 + 3]));
            *(float4*)&dst[32 + c * 4] = make_float4(
                __uint_as_float(d1[c * 4]), __uint_as_float(d1[c * 4 + 1]),
                __uint_as_float(d1[c * 4 + 2]), __uint_as_float(d1[c * 4 + 3]));
        }
    }
    __syncthreads();
    if (wid == 0) tmem_dealloc(tmem, 64);

#else  // ------------------- FMA fallback (non-'a' pass) -------------------
    ull*   wT = (ull*)(smem + SMF_WT);
    float* hs = (float*)(smem + SMF_HS);

    const int rowA = tid >> 1;
    const int jh   = (tid & 1) * 16;
    const float s1r = g_s1[row0 + rowA];
    const int*   adjRow = adj + (size_t)(row0 + rowA) * N_NODES + jbase + jh;
    const float* s2p    = g_s2 + jbase + jh;
    float lpart = 0.f;

    const int rg = tid >> 4;
    const int fg = tid & 15;
    ull acc[16];
#pragma unroll
    for (int i = 0; i < 16; i++) acc[i] = 0ull;

    const int hjl = tid >> 4;
    const int hf4 = tid & 15;

    for (int t = 0; t < NT_F; t++) {
        const int jt = jbase + t * BJ_F;
        const int4* ap = (const int4*)(adjRow + t * BJ_F);
        int4 A0 = ap[0], A1 = ap[1], A2 = ap[2], A3 = ap[3];
        float4 S0 = *(const float4*)(s2p + t * BJ_F);
        float4 S1 = *(const float4*)(s2p + t * BJ_F + 4);
        float4 S2 = *(const float4*)(s2p + t * BJ_F + 8);
        float4 S3 = *(const float4*)(s2p + t * BJ_F + 12);
        float4 H0 = *(const float4*)&g_h[(size_t)(jt + hjl) * F_OUT + hf4 * 4];
        float4 H1 = *(const float4*)&g_h[(size_t)(jt + 16 + hjl) * F_OUT + hf4 * 4];

        __syncthreads();

        *(float4*)&hs[hjl * HS_PITCH + hf4 * 4]        = H0;
        *(float4*)&hs[(16 + hjl) * HS_PITCH + hf4 * 4] = H1;

        int   av[16]; float sv[16];
        *(int4*)&av[0] = A0; *(int4*)&av[4] = A1; *(int4*)&av[8] = A2; *(int4*)&av[12] = A3;
        *(float4*)&sv[0] = S0; *(float4*)&sv[4] = S1; *(float4*)&sv[8] = S2; *(float4*)&sv[12] = S3;

#pragma unroll
        for (int jj = 0; jj < 16; jj++) {
            float e  = s1r + sv[jj];
            float le = fmaxf(e, 0.2f * e);
            float w  = __expf(le);
            w = (av[jj] > 0) ? w : 0.f;
            lpart += w;
            wT[(jh + jj) * WT_PITCH + rowA] = dup2(w);
        }
        __syncthreads();

#pragma unroll 4
        for (int jj = 0; jj < BJ_F; jj++) {
            const ulonglong2* wp = (const ulonglong2*)&wT[jj * WT_PITCH + rg * 8];
            ulonglong2 w01 = wp[0], w23 = wp[1], w45 = wp[2], w67 = wp[3];
            ulonglong2 hv  = *(const ulonglong2*)&hs[jj * HS_PITCH + fg * 4];
            ffma2(acc[0],  w01.x, hv.x); ffma2(acc[1],  w01.x, hv.y);
            ffma2(acc[2],  w01.y, hv.x); ffma2(acc[3],  w01.y, hv.y);
            ffma2(acc[4],  w23.x, hv.x); ffma2(acc[5],  w23.x, hv.y);
            ffma2(acc[6],  w23.y, hv.x); ffma2(acc[7],  w23.y, hv.y);
            ffma2(acc[8],  w45.x, hv.x); ffma2(acc[9],  w45.x, hv.y);
            ffma2(acc[10], w45.y, hv.x); ffma2(acc[11], w45.y, hv.y);
            ffma2(acc[12], w67.x, hv.x); ffma2(acc[13], w67.x, hv.y);
            ffma2(acc[14], w67.y, hv.x); ffma2(acc[15], w67.y, hv.y);
        }
    }

    float lo2 = __shfl_xor_sync(0xffffffffu, lpart, 1);
    if ((tid & 1) == 0) g_lP[s][row0 + rowA] = lpart + lo2;

    float* ap2 = g_accP[s];
#pragma unroll
    for (int r = 0; r < 8; r++) {
        float2 x = unpack2(acc[r * 2]);
        float2 y = unpack2(acc[r * 2 + 1]);
        float4 o = make_float4(x.x, x.y, y.x, y.y);
        *(float4*)&ap2[(size_t)(row0 + rg * 8 + r) * F_OUT + fg * 4] = o;
    }
#endif
}

// ---------------------------------------------------------------------------
// Kernel 3: out[i][f] = sum_s accP[s][i][f] / sum_s lP[s][i]  (float4)
// ---------------------------------------------------------------------------
__global__ __launch_bounds__(256) void k_norm(float* __restrict__ out) {
    const int idx = blockIdx.x * 256 + threadIdx.x;
    const int i = idx >> 4;
    float4 v0 = ((const float4*)g_accP[0])[idx];
    float4 v1 = ((const float4*)g_accP[1])[idx];
    float4 v2 = ((const float4*)g_accP[2])[idx];
    float4 v3 = ((const float4*)g_accP[3])[idx];
    float inv = 1.f / ((g_lP[0][i] + g_lP[1][i]) + (g_lP[2][i] + g_lP[3][i]));
    float4 o = make_float4(((v0.x + v1.x) + (v2.x + v3.x)) * inv,
                           ((v0.y + v1.y) + (v2.y + v3.y)) * inv,
                           ((v0.z + v1.z) + (v2.z + v3.z)) * inv,
                           ((v0.w + v1.w) + (v2.w + v3.w)) * inv);
    ((float4*)out)[idx] = o;
}

extern "C" void kernel_launch(void* const* d_in, const int* in_sizes, int n_in,
                              void* d_out, int out_size) {
    const float* inp = (const float*)d_in[0];
    const int*   adj = (const int*)d_in[1];
    const float* W   = (const float*)d_in[2];
    const float* a   = (const float*)d_in[3];
    float* out = (float*)d_out;

    cudaFuncSetAttribute(k_hproj_tc, cudaFuncAttributeMaxDynamicSharedMemorySize, HP_SMTOT);
    cudaFuncSetAttribute(k_attn_tc, cudaFuncAttributeMaxDynamicSharedMemorySize, SM_TOT);

    k_wprep<<<64, 512>>>(W);
    dim3 gh(N_NODES / 128, KSPLIT_H);
    k_hproj_tc<<<gh, NTHR_H, HP_SMTOT>>>(inp, W);
    k_hmerge<<<N_NODES / 128, 512>>>(a);
    dim3 g2(N_NODES / BM, NSPLIT);
    k_attn_tc<<<g2, NTHR_A, SM_TOT>>>(adj);
    k_norm<<<(N_NODES * F_OUT / 4) / 256, 256>>>(out);
}